// round 16
// baseline (speedup 1.0000x reference)
#include <cuda_runtime.h>
#include <cuda_fp16.h>
#include <math.h>
#include <stdint.h>

#define TOKENS 4096
#define HID    4096
#define NEXP   4
#define FDIM   8192
#define OUTD   1792

// GEMM tiling: CTA 128x128, 128 threads, 4 warps @ 64x64, BK=32, NS=5,
// frag double buffering, one wait+sync per tile, 2 CTAs/SM.
#define BMM 128
#define BNN 128
#define ASTRB 80                      // A smem row stride bytes (64B data + 16 pad)
#define BSTRB 272                     // B smem row stride bytes (256B data + 16 pad)
#define A_ST (BMM * ASTRB)            // 10240
#define B_ST (32 * BSTRB)             // 8704
#define STAGE (A_ST + B_ST)           // 18944
#define NS 5
#define SMEM_DYN (NS * STAGE)         // 94720 (x2 CTAs = 189.4KB)

// ---------------- scratch (device globals) ----------------
__device__ __align__(1024) __half g_hs16[(size_t)TOKENS * HID];          // 33.5MB
__device__ __align__(1024) __half g_W1h[(size_t)NEXP * HID * FDIM];      // 268MB
__device__ __align__(1024) __half g_W2h[(size_t)NEXP * FDIM * OUTD];     // 117MB
__device__ __align__(1024) __half g_H[(size_t)NEXP * TOKENS * FDIM];     // 268MB
__device__ __align__(1024) float  g_Y[(size_t)2 * TOKENS * OUTD];        // 56MB
__device__ __align__(256) float g_gates[2 * TOKENS];
__device__ __align__(256) int   g_rows[NEXP * TOKENS];
__device__ __align__(256) int   g_cnt[NEXP];

// ---------------- helpers ----------------
__device__ __forceinline__ uint32_t smem_u32(const void* p) {
    uint32_t a;
    asm("{ .reg .u64 t; cvta.to.shared.u64 t, %1; cvt.u32.u64 %0, t; }" : "=r"(a) : "l"(p));
    return a;
}
__device__ __forceinline__ void cpa16(uint32_t dst, const void* src) {
    asm volatile("cp.async.cg.shared.global [%0], [%1], 16;" :: "r"(dst), "l"(src));
}
__device__ __forceinline__ float gelu_exact(float x) {
    return 0.5f * x * (1.0f + erff(x * 0.70710678118654752440f));
}
__device__ __forceinline__ uint4 ldsm4(uint32_t a) {
    uint4 r;
    asm volatile("ldmatrix.sync.aligned.m8n8.x4.shared.b16 {%0,%1,%2,%3}, [%4];"
                 : "=r"(r.x), "=r"(r.y), "=r"(r.z), "=r"(r.w) : "r"(a));
    return r;
}
__device__ __forceinline__ uint4 ldsm4t(uint32_t a) {
    uint4 r;
    asm volatile("ldmatrix.sync.aligned.m8n8.x4.trans.shared.b16 {%0,%1,%2,%3}, [%4];"
                 : "=r"(r.x), "=r"(r.y), "=r"(r.z), "=r"(r.w) : "r"(a));
    return r;
}
__device__ __forceinline__ void mma_f16(float c[4],
                                        uint32_t a0, uint32_t a1, uint32_t a2, uint32_t a3,
                                        uint32_t b0, uint32_t b1) {
    asm volatile(
        "mma.sync.aligned.m16n8k16.row.col.f32.f16.f16.f32 "
        "{%0,%1,%2,%3}, {%4,%5,%6,%7}, {%8,%9}, {%0,%1,%2,%3};\n"
        : "+f"(c[0]), "+f"(c[1]), "+f"(c[2]), "+f"(c[3])
        : "r"(a0), "r"(a1), "r"(a2), "r"(a3), "r"(b0), "r"(b1));
}

// ---------------- router: 1 warp per token ----------------
__global__ void __launch_bounds__(256) router_kernel(
    const float* __restrict__ hs, const float* __restrict__ rw,
    const float* __restrict__ rb, int* __restrict__ cnt,
    int* __restrict__ rows, float* __restrict__ gates) {
    int warp = threadIdx.x >> 5;
    int lane = threadIdx.x & 31;
    int t = blockIdx.x * 8 + warp;
    if (t >= TOKENS) return;

    float a0 = 0.f, a1 = 0.f, a2 = 0.f, a3 = 0.f;
    const float4* x = (const float4*)(hs + (size_t)t * HID);
    const float4* w = (const float4*)rw;
    #pragma unroll 4
    for (int i = lane; i < HID / 4; i += 32) {
        float4 v = x[i];
        float4 w0 = w[4 * i + 0];
        float4 w1 = w[4 * i + 1];
        float4 w2 = w[4 * i + 2];
        float4 w3 = w[4 * i + 3];
        a0 += v.x * w0.x + v.y * w1.x + v.z * w2.x + v.w * w3.x;
        a1 += v.x * w0.y + v.y * w1.y + v.z * w2.y + v.w * w3.y;
        a2 += v.x * w0.z + v.y * w1.z + v.z * w2.z + v.w * w3.z;
        a3 += v.x * w0.w + v.y * w1.w + v.z * w2.w + v.w * w3.w;
    }
    #pragma unroll
    for (int s = 16; s > 0; s >>= 1) {
        a0 += __shfl_xor_sync(0xffffffffu, a0, s);
        a1 += __shfl_xor_sync(0xffffffffu, a1, s);
        a2 += __shfl_xor_sync(0xffffffffu, a2, s);
        a3 += __shfl_xor_sync(0xffffffffu, a3, s);
    }
    if (lane == 0) {
        float l[NEXP] = {a0 + rb[0], a1 + rb[1], a2 + rb[2], a3 + rb[3]};
        int i0 = 0;
        #pragma unroll
        for (int e = 1; e < NEXP; e++)
            if (l[e] > l[i0]) i0 = e;
        int i1 = -1;
        #pragma unroll
        for (int e = 0; e < NEXP; e++) {
            if (e == i0) continue;
            if (i1 < 0 || l[e] > l[i1]) i1 = e;
        }
        float q = expf(l[i1] - l[i0]);  // <= 1
        float g0 = 1.0f / (1.0f + q);
        float g1 = q / (1.0f + q);
        int p0 = atomicAdd(&cnt[i0], 1);
        rows[i0 * TOKENS + p0] = 2 * t;
        int p1 = atomicAdd(&cnt[i1], 1);
        rows[i1 * TOKENS + p1] = 2 * t + 1;
        gates[2 * t] = g0;
        gates[2 * t + 1] = g1;
    }
}

// ---------------- streaming fp32 -> fp16 convert (optionally zeroes cnt) ----------------
__global__ void __launch_bounds__(256) cvt_kernel(
    const float* __restrict__ src, __half* __restrict__ dst, size_t n8,
    int* cnt_to_zero) {
    size_t idx = (size_t)blockIdx.x * 256 + threadIdx.x;
    if (cnt_to_zero && blockIdx.x == 0 && threadIdx.x < NEXP)
        cnt_to_zero[threadIdx.x] = 0;
    if (idx >= n8) return;
    const float4* s = (const float4*)(src + idx * 8);
    float4 v0 = s[0], v1 = s[1];
    __half h[8];
    h[0] = __float2half_rn(v0.x); h[1] = __float2half_rn(v0.y);
    h[2] = __float2half_rn(v0.z); h[3] = __float2half_rn(v0.w);
    h[4] = __float2half_rn(v1.x); h[5] = __float2half_rn(v1.y);
    h[6] = __float2half_rn(v1.z); h[7] = __float2half_rn(v1.w);
    *(uint4*)(dst + idx * 8) = *(uint4*)h;
}

// ---------------- fp16 tensor-core GEMM, 64x64 warp tiles, 2 CTAs/SM ----------------
// CTA 128x128, 4 warps (wm 0..1, wn 0..1), BK=32, NS=5, wait->sync per tile.
// grid: x = m-tiles (fast; shares B slab in L2), y = n-tiles, z = expert.
template <bool GATHER, bool GELU>
__global__ void __launch_bounds__(128, 2) gemm16_kernel(
    const __half* __restrict__ Ab, const __half* __restrict__ Bb,
    const float* __restrict__ bias, void* __restrict__ OutV,
    const int* __restrict__ rows_list, const int* __restrict__ cnt,
    int N, int K) {
    const int e = blockIdx.z;
    const int m0 = blockIdx.x * BMM;
    const int cn = cnt[e];
    if (m0 >= cn) return;
    const int n0 = blockIdx.y * BNN;

    extern __shared__ __align__(16) char sh[];
    const uint32_t sb = smem_u32(sh);

    const int tid = threadIdx.x;
    const int lane = tid & 31;
    const int warp = tid >> 5;       // 0..3
    const int g = lane >> 2;
    const int t = lane & 3;
    const int wm = warp >> 1;        // 0..1 -> m offset 64*wm
    const int wn = warp & 1;         // 0..1 -> n offset 64*wn

    // staging source pointers
    // A: 128 rows x 64B -> 1 row/thread, 4 cpa along the row
    int pc = m0 + tid;
    int pcl = pc < cn - 1 ? pc : cn - 1;
    size_t arow = GATHER ? (size_t)(rows_list[e * TOKENS + pcl] >> 1)
                         : (size_t)(e * TOKENS + pcl);
    const __half* aptr = Ab + arow * (size_t)K;
    // B: 32 rows x 256B -> row = tid>>2, seg = (tid&3)*64B, 4 cpa
    const __half* bptr = Bb + ((size_t)e * K + (tid >> 2)) * N + n0 + (tid & 3) * 32;

    // staging dst offsets
    const uint32_t adst = sb + tid * ASTRB;
    const uint32_t bdst = sb + A_ST + (tid >> 2) * BSTRB + (tid & 3) * 64;

    // ldmatrix per-lane offsets
    const uint32_t a_lane = (lane & 15) * ASTRB + (lane >> 4) * 16;
    const uint32_t b_lane = ((lane & 7) + 8 * ((lane >> 3) & 1)) * BSTRB + (lane >> 4) * 16;

    float c[4][8][4];
    #pragma unroll
    for (int mi = 0; mi < 4; mi++)
        #pragma unroll
        for (int ni = 0; ni < 8; ni++)
            #pragma unroll
            for (int r = 0; r < 4; r++) c[mi][ni][r] = 0.f;

    const int KT = K / 32;

    #define ISSUE(kt, st) do { \
        uint32_t sa = adst + (st) * STAGE; \
        uint32_t sbs = bdst + (st) * STAGE; \
        const __half* as_ = aptr + (size_t)(kt) * 32; \
        const __half* bs_ = bptr + (size_t)(kt) * 32 * N; \
        cpa16(sa, as_); \
        cpa16(sa + 16, as_ + 8); \
        cpa16(sa + 32, as_ + 16); \
        cpa16(sa + 48, as_ + 24); \
        cpa16(sbs, bs_); \
        cpa16(sbs + 16, bs_ + 8); \
        cpa16(sbs + 32, bs_ + 16); \
        cpa16(sbs + 48, bs_ + 24); \
    } while (0)

    #define LOAD_FRAGS(af, bf, st, ks) do { \
        const uint32_t stA_ = sb + (st) * STAGE; \
        const uint32_t ab_ = stA_ + a_lane + (ks) * 32 + wm * 64 * ASTRB; \
        af[0] = ldsm4(ab_); \
        af[1] = ldsm4(ab_ + 16 * ASTRB); \
        af[2] = ldsm4(ab_ + 32 * ASTRB); \
        af[3] = ldsm4(ab_ + 48 * ASTRB); \
        const uint32_t bbs_ = stA_ + A_ST + b_lane + (ks) * 16 * BSTRB + wn * 128; \
        bf[0] = ldsm4t(bbs_); \
        bf[1] = ldsm4t(bbs_ + 32); \
        bf[2] = ldsm4t(bbs_ + 64); \
        bf[3] = ldsm4t(bbs_ + 96); \
    } while (0)

    #define MMA_FRAGS(af, bf) do { \
        _Pragma("unroll") \
        for (int mi = 0; mi < 4; mi++) { \
            _Pragma("unroll") \
            for (int nj = 0; nj < 4; nj++) { \
                mma_f16(c[mi][2 * nj], af[mi].x, af[mi].y, af[mi].z, af[mi].w, \
                        bf[nj].x, bf[nj].y); \
                mma_f16(c[mi][2 * nj + 1], af[mi].x, af[mi].y, af[mi].z, af[mi].w, \
                        bf[nj].z, bf[nj].w); \
            } \
        } \
    } while (0)

    // prologue: tiles 0..3 into stages 0..3 (4 groups)
    #pragma unroll
    for (int kt = 0; kt < NS - 1; kt++) {
        ISSUE(kt, kt);
        asm volatile("cp.async.commit_group;" ::: "memory");
    }
    asm volatile("cp.async.wait_group 3;" ::: "memory");  // tile 0 done (own)
    __syncthreads();                                       // visible to all

    uint4 afA[4], bfA[4], afB[4], bfB[4];
    LOAD_FRAGS(afA, bfA, 0, 0);

    int s_cons = 0;       // stage holding tile kt
    int s_fill = NS - 1;  // stage to refill this iteration

    for (int kt = 0; kt < KT; kt++) {
        // half-step 1 frags of tile kt; ldsm covered by mma of half-step 0
        LOAD_FRAGS(afB, bfB, s_cons, 1);
        MMA_FRAGS(afA, bfA);

        // make tile kt+1 resident AND visible before any read of its stage
        asm volatile("cp.async.wait_group 2;" ::: "memory");
        __syncthreads();

        // refill stage of tile kt-1 (its last read preceded iter kt-1's sync)
        int kn = kt + NS - 1;
        if (kn < KT) ISSUE(kn, s_fill);
        asm volatile("cp.async.commit_group;" ::: "memory");

        // prefetch next tile's half-step 0 frags, covered by mma of half-step 1
        int s_next = s_cons + 1 == NS ? 0 : s_cons + 1;
        if (kt + 1 < KT) LOAD_FRAGS(afA, bfA, s_next, 0);
        MMA_FRAGS(afB, bfB);

        s_cons = s_next;
        if (++s_fill == NS) s_fill = 0;
    }
    #undef ISSUE
    #undef LOAD_FRAGS
    #undef MMA_FRAGS

    // epilogue
    #pragma unroll
    for (int mi = 0; mi < 4; mi++) {
        int p0 = m0 + wm * 64 + mi * 16 + g;
        int p1 = p0 + 8;
        bool v0 = p0 < cn, v1 = p1 < cn;
        int s0 = 0, s1 = 0;
        if (!GELU) {
            s0 = v0 ? rows_list[e * TOKENS + p0] : 0;
            s1 = v1 ? rows_list[e * TOKENS + p1] : 0;
        }
        #pragma unroll
        for (int ni = 0; ni < 8; ni++) {
            int col = n0 + wn * 64 + ni * 8 + 2 * t;
            float2 bv = *(const float2*)(bias + (size_t)e * N + col);
            float x0 = c[mi][ni][0] + bv.x;
            float x1 = c[mi][ni][1] + bv.y;
            float x2 = c[mi][ni][2] + bv.x;
            float x3 = c[mi][ni][3] + bv.y;
            if (GELU) {
                __half* H = (__half*)OutV;
                if (v0) {
                    __half2 h = __floats2half2_rn(gelu_exact(x0), gelu_exact(x1));
                    *(__half2*)(H + ((size_t)e * TOKENS + p0) * N + col) = h;
                }
                if (v1) {
                    __half2 h = __floats2half2_rn(gelu_exact(x2), gelu_exact(x3));
                    *(__half2*)(H + ((size_t)e * TOKENS + p1) * N + col) = h;
                }
            } else {
                float* Y = (float*)OutV;
                if (v0) *(float2*)(Y + (size_t)s0 * N + col) = make_float2(x0, x1);
                if (v1) *(float2*)(Y + (size_t)s1 * N + col) = make_float2(x2, x3);
            }
        }
    }
}

// ---------------- combine: out[t] = g0*Y[2t] + g1*Y[2t+1] ----------------
__global__ void __launch_bounds__(256) combine_kernel(
    const float* __restrict__ Y, const float* __restrict__ gates,
    float* __restrict__ out) {
    int idx = blockIdx.x * blockDim.x + threadIdx.x;
    const int JW = OUTD / 4;  // 448
    if (idx >= TOKENS * JW) return;
    int t = idx / JW;
    int j = idx - t * JW;
    float g0 = gates[2 * t];
    float g1 = gates[2 * t + 1];
    float4 y0 = ((const float4*)(Y + (size_t)(2 * t) * OUTD))[j];
    float4 y1 = ((const float4*)(Y + (size_t)(2 * t + 1) * OUTD))[j];
    float4 o;
    o.x = g0 * y0.x + g1 * y1.x;
    o.y = g0 * y0.y + g1 * y1.y;
    o.z = g0 * y0.z + g1 * y1.z;
    o.w = g0 * y0.w + g1 * y1.w;
    ((float4*)(out + (size_t)t * OUTD))[j] = o;
}

// ---------------- launch ----------------
extern "C" void kernel_launch(void* const* d_in, const int* in_sizes, int n_in,
                              void* d_out, int out_size) {
    const float* hs = (const float*)d_in[0];
    const float* rw = (const float*)d_in[1];
    const float* rb = (const float*)d_in[2];
    const float* w1 = (const float*)d_in[3];
    const float* b1 = (const float*)d_in[4];
    const float* w2 = (const float*)d_in[5];
    const float* b2 = (const float*)d_in[6];
    float* out = (float*)d_out;

    __half *hs16, *W1h, *W2h, *H;
    float *Y, *gates;
    int *cnt, *rows;
    cudaGetSymbolAddress((void**)&hs16, g_hs16);
    cudaGetSymbolAddress((void**)&W1h, g_W1h);
    cudaGetSymbolAddress((void**)&W2h, g_W2h);
    cudaGetSymbolAddress((void**)&H, g_H);
    cudaGetSymbolAddress((void**)&Y, g_Y);
    cudaGetSymbolAddress((void**)&gates, g_gates);
    cudaGetSymbolAddress((void**)&cnt, g_cnt);
    cudaGetSymbolAddress((void**)&rows, g_rows);

    cudaFuncSetAttribute((const void*)gemm16_kernel<true, true>,
                         cudaFuncAttributeMaxDynamicSharedMemorySize, SMEM_DYN);
    cudaFuncSetAttribute((const void*)gemm16_kernel<false, false>,
                         cudaFuncAttributeMaxDynamicSharedMemorySize, SMEM_DYN);

    size_t n_hs = (size_t)TOKENS * HID / 8;
    size_t n_w1 = (size_t)NEXP * HID * FDIM / 8;
    size_t n_w2 = (size_t)NEXP * FDIM * OUTD / 8;

    // Same 7-launch order so ncu captures GEMM1 (our index 3).
    cvt_kernel<<<(unsigned)((n_w1 + 255) / 256), 256>>>(w1, W1h, n_w1, cnt);   // 0 (+zero cnt)
    router_kernel<<<TOKENS / 8, 256>>>(hs, rw, rb, cnt, rows, gates);          // 1
    cvt_kernel<<<(unsigned)((n_hs + 255) / 256), 256>>>(hs, hs16, n_hs, 0);    // 2
    // GEMM1 (our 3): hs16 (gathered rows) x W1h[E][HID][FDIM] -> GELU -> H fp16
    gemm16_kernel<true, true><<<dim3(TOKENS / BMM, FDIM / BNN, NEXP), 128, SMEM_DYN>>>(
        hs16, W1h, b1, (void*)H, rows, cnt, FDIM, HID);
    cvt_kernel<<<(unsigned)((n_w2 + 255) / 256), 256>>>(w2, W2h, n_w2, 0);     // 4
    // GEMM2: H x W2h[E][FDIM][OUTD] -> Y fp32 (scattered by slot)
    gemm16_kernel<false, false><<<dim3(TOKENS / BMM, OUTD / BNN, NEXP), 128, SMEM_DYN>>>(
        H, W2h, b2, (void*)Y, rows, cnt, OUTD, FDIM);
    combine_kernel<<<(TOKENS * (OUTD / 4) + 255) / 256, 256>>>(Y, gates, out);
}

// round 17
// speedup vs baseline: 1.2620x; 1.2620x over previous
#include <cuda_runtime.h>
#include <cuda_fp16.h>
#include <math.h>
#include <stdint.h>

#define TOKENS 4096
#define HID    4096
#define NEXP   4
#define FDIM   8192
#define OUTD   1792

// GEMM tiling (R14 champion): CTA 128x256, BK=32 halves, 8 warps @ 64x64,
// 6-stage cp.async, frag double buffering, one wait+sync per k-tile, 1 CTA/SM.
#define BMM 128
#define BNN 256
#define ASTRB 80                      // A smem row stride bytes (64B data + 16 pad)
#define BSTRB 528                     // B smem row stride bytes (512B data + 16 pad)
#define A_ST (BMM * ASTRB)            // 10240
#define B_ST (32 * BSTRB)             // 16896
#define STAGE (A_ST + B_ST)           // 27136
#define NS 6
#define SMEM_DYN (NS * STAGE)         // 162816 (1 CTA/SM)

// ---------------- scratch (device globals) ----------------
__device__ __align__(1024) __half g_hs16[(size_t)TOKENS * HID];          // 33.5MB
__device__ __align__(1024) __half g_W1h[(size_t)NEXP * HID * FDIM];      // 268MB
__device__ __align__(1024) __half g_W2h[(size_t)NEXP * FDIM * OUTD];     // 117MB
__device__ __align__(1024) __half g_H[(size_t)NEXP * TOKENS * FDIM];     // 268MB
__device__ __align__(1024) float  g_Y[(size_t)2 * TOKENS * OUTD];        // 56MB
__device__ __align__(256) float g_gates[2 * TOKENS];
__device__ __align__(256) int   g_rows[NEXP * TOKENS];
__device__ __align__(256) int   g_cnt[NEXP];

// ---------------- helpers ----------------
__device__ __forceinline__ uint32_t smem_u32(const void* p) {
    uint32_t a;
    asm("{ .reg .u64 t; cvta.to.shared.u64 t, %1; cvt.u32.u64 %0, t; }" : "=r"(a) : "l"(p));
    return a;
}
__device__ __forceinline__ void cpa16(uint32_t dst, const void* src) {
    asm volatile("cp.async.cg.shared.global [%0], [%1], 16;" :: "r"(dst), "l"(src));
}
__device__ __forceinline__ float gelu_exact(float x) {
    return 0.5f * x * (1.0f + erff(x * 0.70710678118654752440f));
}
__device__ __forceinline__ uint4 ldsm4(uint32_t a) {
    uint4 r;
    asm volatile("ldmatrix.sync.aligned.m8n8.x4.shared.b16 {%0,%1,%2,%3}, [%4];"
                 : "=r"(r.x), "=r"(r.y), "=r"(r.z), "=r"(r.w) : "r"(a));
    return r;
}
__device__ __forceinline__ uint4 ldsm4t(uint32_t a) {
    uint4 r;
    asm volatile("ldmatrix.sync.aligned.m8n8.x4.trans.shared.b16 {%0,%1,%2,%3}, [%4];"
                 : "=r"(r.x), "=r"(r.y), "=r"(r.z), "=r"(r.w) : "r"(a));
    return r;
}
__device__ __forceinline__ void mma_f16(float c[4],
                                        uint32_t a0, uint32_t a1, uint32_t a2, uint32_t a3,
                                        uint32_t b0, uint32_t b1) {
    asm volatile(
        "mma.sync.aligned.m16n8k16.row.col.f32.f16.f16.f32 "
        "{%0,%1,%2,%3}, {%4,%5,%6,%7}, {%8,%9}, {%0,%1,%2,%3};\n"
        : "+f"(c[0]), "+f"(c[1]), "+f"(c[2]), "+f"(c[3])
        : "r"(a0), "r"(a1), "r"(a2), "r"(a3), "r"(b0), "r"(b1));
}

// ---------------- router: 1 warp per token; also emits hs16 (fp16 rn) ----------------
__global__ void __launch_bounds__(256) router_kernel(
    const float* __restrict__ hs, const float* __restrict__ rw,
    const float* __restrict__ rb, int* __restrict__ cnt,
    int* __restrict__ rows, float* __restrict__ gates,
    __half* __restrict__ hs16) {
    int warp = threadIdx.x >> 5;
    int lane = threadIdx.x & 31;
    int t = blockIdx.x * 8 + warp;
    if (t >= TOKENS) return;

    float a0 = 0.f, a1 = 0.f, a2 = 0.f, a3 = 0.f;
    const float4* x = (const float4*)(hs + (size_t)t * HID);
    __half* h16 = hs16 + (size_t)t * HID;
    const float4* w = (const float4*)rw;
    #pragma unroll 4
    for (int i = lane; i < HID / 4; i += 32) {
        float4 v = x[i];
        // emit fp16 copy (rn) for the GEMM1 A operand
        __half hv[4];
        hv[0] = __float2half_rn(v.x);
        hv[1] = __float2half_rn(v.y);
        hv[2] = __float2half_rn(v.z);
        hv[3] = __float2half_rn(v.w);
        *(uint2*)(h16 + i * 4) = *(uint2*)hv;
        float4 w0 = w[4 * i + 0];
        float4 w1 = w[4 * i + 1];
        float4 w2 = w[4 * i + 2];
        float4 w3 = w[4 * i + 3];
        a0 += v.x * w0.x + v.y * w1.x + v.z * w2.x + v.w * w3.x;
        a1 += v.x * w0.y + v.y * w1.y + v.z * w2.y + v.w * w3.y;
        a2 += v.x * w0.z + v.y * w1.z + v.z * w2.z + v.w * w3.z;
        a3 += v.x * w0.w + v.y * w1.w + v.z * w2.w + v.w * w3.w;
    }
    #pragma unroll
    for (int s = 16; s > 0; s >>= 1) {
        a0 += __shfl_xor_sync(0xffffffffu, a0, s);
        a1 += __shfl_xor_sync(0xffffffffu, a1, s);
        a2 += __shfl_xor_sync(0xffffffffu, a2, s);
        a3 += __shfl_xor_sync(0xffffffffu, a3, s);
    }
    if (lane == 0) {
        float l[NEXP] = {a0 + rb[0], a1 + rb[1], a2 + rb[2], a3 + rb[3]};
        int i0 = 0;
        #pragma unroll
        for (int e = 1; e < NEXP; e++)
            if (l[e] > l[i0]) i0 = e;
        int i1 = -1;
        #pragma unroll
        for (int e = 0; e < NEXP; e++) {
            if (e == i0) continue;
            if (i1 < 0 || l[e] > l[i1]) i1 = e;
        }
        float q = expf(l[i1] - l[i0]);  // <= 1
        float g0 = 1.0f / (1.0f + q);
        float g1 = q / (1.0f + q);
        int p0 = atomicAdd(&cnt[i0], 1);
        rows[i0 * TOKENS + p0] = 2 * t;
        int p1 = atomicAdd(&cnt[i1], 1);
        rows[i1 * TOKENS + p1] = 2 * t + 1;
        gates[2 * t] = g0;
        gates[2 * t + 1] = g1;
    }
}

// ---------------- streaming fp32 -> fp16 convert (optionally zeroes cnt) ----------------
__global__ void __launch_bounds__(256) cvt_kernel(
    const float* __restrict__ src, __half* __restrict__ dst, size_t n8,
    int* cnt_to_zero) {
    size_t idx = (size_t)blockIdx.x * 256 + threadIdx.x;
    if (cnt_to_zero && blockIdx.x == 0 && threadIdx.x < NEXP)
        cnt_to_zero[threadIdx.x] = 0;
    if (idx >= n8) return;
    const float4* s = (const float4*)(src + idx * 8);
    float4 v0 = s[0], v1 = s[1];
    __half h[8];
    h[0] = __float2half_rn(v0.x); h[1] = __float2half_rn(v0.y);
    h[2] = __float2half_rn(v0.z); h[3] = __float2half_rn(v0.w);
    h[4] = __float2half_rn(v1.x); h[5] = __float2half_rn(v1.y);
    h[6] = __float2half_rn(v1.z); h[7] = __float2half_rn(v1.w);
    *(uint4*)(dst + idx * 8) = *(uint4*)h;
}

// ---------------- fp16 tensor-core GEMM, 64x64 warp tiles + pipelined frags ----------
// CTA 128x256, 8 warps (wm 0..1 x 64 rows, wn 0..3 x 64 cols), BK=32, NS=6.
// Per tile: LOAD afB(ks1) ; MMA afA ; wait_group 3 ; sync ; ISSUE(kt+5) ; commit ;
//           LOAD afA(tile kt+1, ks0) ; MMA afB.
// grid: x = m-tiles (fast; shares B slab in L2), y = n-tiles, z = expert.
template <bool GATHER, bool GELU>
__global__ void __launch_bounds__(256, 1) gemm16_kernel(
    const __half* __restrict__ Ab, const __half* __restrict__ Bb,
    const float* __restrict__ bias, void* __restrict__ OutV,
    const int* __restrict__ rows_list, const int* __restrict__ cnt,
    int N, int K) {
    const int e = blockIdx.z;
    const int m0 = blockIdx.x * BMM;
    const int cn = cnt[e];
    if (m0 >= cn) return;
    const int n0 = blockIdx.y * BNN;

    extern __shared__ __align__(16) char sh[];
    const uint32_t sb = smem_u32(sh);

    const int tid = threadIdx.x;
    const int lane = tid & 31;
    const int warp = tid >> 5;
    const int g = lane >> 2;
    const int t = lane & 3;
    const int wm = warp >> 2;  // 0..1 -> m offset 64*wm
    const int wn = warp & 3;   // 0..3 -> n offset 64*wn

    // staging source pointers
    // A: 128 rows x 64B -> 2 cpa/thread: row = tid>>1
    int pc = m0 + (tid >> 1);
    int pcl = pc < cn - 1 ? pc : cn - 1;
    size_t arow = GATHER ? (size_t)(rows_list[e * TOKENS + pcl] >> 1)
                         : (size_t)(e * TOKENS + pcl);
    const __half* aptr = Ab + arow * (size_t)K + (tid & 1) * 16;
    // B: 32 rows x 512B -> 4 cpa/thread: row = tid>>3, seg = (tid&7)*64B
    const __half* bptr = Bb + ((size_t)e * K + (tid >> 3)) * N + n0 + (tid & 7) * 32;

    // staging dst offsets
    const uint32_t adst = sb + (tid >> 1) * ASTRB + (tid & 1) * 32;
    const uint32_t bdst = sb + A_ST + (tid >> 3) * BSTRB + (tid & 7) * 64;

    // ldmatrix per-lane offsets
    const uint32_t a_lane = (lane & 15) * ASTRB + (lane >> 4) * 16;
    const uint32_t b_lane = ((lane & 7) + 8 * ((lane >> 3) & 1)) * BSTRB + (lane >> 4) * 16;

    float c[4][8][4];
    #pragma unroll
    for (int mi = 0; mi < 4; mi++)
        #pragma unroll
        for (int ni = 0; ni < 8; ni++)
            #pragma unroll
            for (int r = 0; r < 4; r++) c[mi][ni][r] = 0.f;

    const int KT = K / 32;

    #define ISSUE(kt, st) do { \
        uint32_t sa = adst + (st) * STAGE; \
        uint32_t sbs = bdst + (st) * STAGE; \
        const __half* as_ = aptr + (size_t)(kt) * 32; \
        const __half* bs_ = bptr + (size_t)(kt) * 32 * N; \
        cpa16(sa, as_); \
        cpa16(sa + 16, as_ + 8); \
        cpa16(sbs, bs_); \
        cpa16(sbs + 16, bs_ + 8); \
        cpa16(sbs + 32, bs_ + 16); \
        cpa16(sbs + 48, bs_ + 24); \
    } while (0)

    #define LOAD_FRAGS(af, bf, st, ks) do { \
        const uint32_t stA_ = sb + (st) * STAGE; \
        const uint32_t ab_ = stA_ + a_lane + (ks) * 32 + wm * 64 * ASTRB; \
        af[0] = ldsm4(ab_); \
        af[1] = ldsm4(ab_ + 16 * ASTRB); \
        af[2] = ldsm4(ab_ + 32 * ASTRB); \
        af[3] = ldsm4(ab_ + 48 * ASTRB); \
        const uint32_t bbs_ = stA_ + A_ST + b_lane + (ks) * 16 * BSTRB + wn * 128; \
        bf[0] = ldsm4t(bbs_); \
        bf[1] = ldsm4t(bbs_ + 32); \
        bf[2] = ldsm4t(bbs_ + 64); \
        bf[3] = ldsm4t(bbs_ + 96); \
    } while (0)

    #define MMA_FRAGS(af, bf) do { \
        _Pragma("unroll") \
        for (int mi = 0; mi < 4; mi++) { \
            _Pragma("unroll") \
            for (int nj = 0; nj < 4; nj++) { \
                mma_f16(c[mi][2 * nj], af[mi].x, af[mi].y, af[mi].z, af[mi].w, \
                        bf[nj].x, bf[nj].y); \
                mma_f16(c[mi][2 * nj + 1], af[mi].x, af[mi].y, af[mi].z, af[mi].w, \
                        bf[nj].z, bf[nj].w); \
            } \
        } \
    } while (0)

    // prologue: tiles 0..4 into stages 0..4 (5 groups)
    #pragma unroll
    for (int kt = 0; kt < NS - 1; kt++) {
        ISSUE(kt, kt);
        asm volatile("cp.async.commit_group;" ::: "memory");
    }
    asm volatile("cp.async.wait_group 4;" ::: "memory");  // tile 0 done (own)
    __syncthreads();                                       // visible to all

    uint4 afA[4], bfA[4], afB[4], bfB[4];
    LOAD_FRAGS(afA, bfA, 0, 0);

    int s_cons = 0;       // stage holding tile kt
    int s_fill = NS - 1;  // stage to refill this iteration

    for (int kt = 0; kt < KT; kt++) {
        // half-step 1 frags of tile kt; ldsm covered by mma of half-step 0
        LOAD_FRAGS(afB, bfB, s_cons, 1);
        MMA_FRAGS(afA, bfA);

        // make tile kt+1 resident AND visible before any read of its stage
        asm volatile("cp.async.wait_group 3;" ::: "memory");
        __syncthreads();

        // refill stage of tile kt-1 (its last read preceded iter kt-1's sync)
        int kn = kt + NS - 1;
        if (kn < KT) ISSUE(kn, s_fill);
        asm volatile("cp.async.commit_group;" ::: "memory");

        // prefetch next tile's half-step 0 frags, covered by mma of half-step 1
        int s_next = s_cons + 1 == NS ? 0 : s_cons + 1;
        if (kt + 1 < KT) LOAD_FRAGS(afA, bfA, s_next, 0);
        MMA_FRAGS(afB, bfB);

        s_cons = s_next;
        if (++s_fill == NS) s_fill = 0;
    }
    #undef ISSUE
    #undef LOAD_FRAGS
    #undef MMA_FRAGS

    // epilogue
    #pragma unroll
    for (int mi = 0; mi < 4; mi++) {
        int p0 = m0 + wm * 64 + mi * 16 + g;
        int p1 = p0 + 8;
        bool v0 = p0 < cn, v1 = p1 < cn;
        int s0 = 0, s1 = 0;
        if (!GELU) {
            s0 = v0 ? rows_list[e * TOKENS + p0] : 0;
            s1 = v1 ? rows_list[e * TOKENS + p1] : 0;
        }
        #pragma unroll
        for (int ni = 0; ni < 8; ni++) {
            int col = n0 + wn * 64 + ni * 8 + 2 * t;
            float2 bv = *(const float2*)(bias + (size_t)e * N + col);
            float x0 = c[mi][ni][0] + bv.x;
            float x1 = c[mi][ni][1] + bv.y;
            float x2 = c[mi][ni][2] + bv.x;
            float x3 = c[mi][ni][3] + bv.y;
            if (GELU) {
                __half* H = (__half*)OutV;
                if (v0) {
                    __half2 h = __floats2half2_rn(gelu_exact(x0), gelu_exact(x1));
                    *(__half2*)(H + ((size_t)e * TOKENS + p0) * N + col) = h;
                }
                if (v1) {
                    __half2 h = __floats2half2_rn(gelu_exact(x2), gelu_exact(x3));
                    *(__half2*)(H + ((size_t)e * TOKENS + p1) * N + col) = h;
                }
            } else {
                float* Y = (float*)OutV;
                if (v0) *(float2*)(Y + (size_t)s0 * N + col) = make_float2(x0, x1);
                if (v1) *(float2*)(Y + (size_t)s1 * N + col) = make_float2(x2, x3);
            }
        }
    }
}

// ---------------- combine: out[t] = g0*Y[2t] + g1*Y[2t+1] ----------------
__global__ void __launch_bounds__(256) combine_kernel(
    const float* __restrict__ Y, const float* __restrict__ gates,
    float* __restrict__ out) {
    int idx = blockIdx.x * blockDim.x + threadIdx.x;
    const int JW = OUTD / 4;  // 448
    if (idx >= TOKENS * JW) return;
    int t = idx / JW;
    int j = idx - t * JW;
    float g0 = gates[2 * t];
    float g1 = gates[2 * t + 1];
    float4 y0 = ((const float4*)(Y + (size_t)(2 * t) * OUTD))[j];
    float4 y1 = ((const float4*)(Y + (size_t)(2 * t + 1) * OUTD))[j];
    float4 o;
    o.x = g0 * y0.x + g1 * y1.x;
    o.y = g0 * y0.y + g1 * y1.y;
    o.z = g0 * y0.z + g1 * y1.z;
    o.w = g0 * y0.w + g1 * y1.w;
    ((float4*)(out + (size_t)t * OUTD))[j] = o;
}

// ---------------- launch ----------------
extern "C" void kernel_launch(void* const* d_in, const int* in_sizes, int n_in,
                              void* d_out, int out_size) {
    const float* hs = (const float*)d_in[0];
    const float* rw = (const float*)d_in[1];
    const float* rb = (const float*)d_in[2];
    const float* w1 = (const float*)d_in[3];
    const float* b1 = (const float*)d_in[4];
    const float* w2 = (const float*)d_in[5];
    const float* b2 = (const float*)d_in[6];
    float* out = (float*)d_out;

    __half *hs16, *W1h, *W2h, *H;
    float *Y, *gates;
    int *cnt, *rows;
    cudaGetSymbolAddress((void**)&hs16, g_hs16);
    cudaGetSymbolAddress((void**)&W1h, g_W1h);
    cudaGetSymbolAddress((void**)&W2h, g_W2h);
    cudaGetSymbolAddress((void**)&H, g_H);
    cudaGetSymbolAddress((void**)&Y, g_Y);
    cudaGetSymbolAddress((void**)&gates, g_gates);
    cudaGetSymbolAddress((void**)&cnt, g_cnt);
    cudaGetSymbolAddress((void**)&rows, g_rows);

    cudaFuncSetAttribute((const void*)gemm16_kernel<true, true>,
                         cudaFuncAttributeMaxDynamicSharedMemorySize, SMEM_DYN);
    cudaFuncSetAttribute((const void*)gemm16_kernel<false, false>,
                         cudaFuncAttributeMaxDynamicSharedMemorySize, SMEM_DYN);

    size_t n_w1 = (size_t)NEXP * HID * FDIM / 8;
    size_t n_w2 = (size_t)NEXP * FDIM * OUTD / 8;

    // Order keeps GEMM1 at our launch index 3 (the slot ncu captures).
    cvt_kernel<<<(unsigned)((n_w1 + 255) / 256), 256>>>(w1, W1h, n_w1, cnt);     // 0 (+zero cnt)
    router_kernel<<<TOKENS / 8, 256>>>(hs, rw, rb, cnt, rows, gates, hs16);      // 1 (+hs16)
    cvt_kernel<<<(unsigned)((n_w2 + 255) / 256), 256>>>(w2, W2h, n_w2, 0);       // 2
    // GEMM1 (our 3): hs16 (gathered rows) x W1h[E][HID][FDIM] -> GELU -> H fp16
    gemm16_kernel<true, true><<<dim3(TOKENS / BMM, FDIM / BNN, NEXP), 256, SMEM_DYN>>>(
        hs16, W1h, b1, (void*)H, rows, cnt, FDIM, HID);
    // GEMM2: H x W2h[E][FDIM][OUTD] -> Y fp32 (scattered by slot)
    gemm16_kernel<false, false><<<dim3(TOKENS / BMM, OUTD / BNN, NEXP), 256, SMEM_DYN>>>(
        H, W2h, b2, (void*)Y, rows, cnt, OUTD, FDIM);
    combine_kernel<<<(TOKENS * (OUTD / 4) + 255) / 256, 256>>>(Y, gates, out);
}